// round 3
// baseline (speedup 1.0000x reference)
#include <cuda_runtime.h>
#include <cstdint>

#define BATCH   2048
#define INST    2
#define IN_AE   1024
#define H_AE    16384
#define NROWS   (BATCH*INST)            /* 4096 */
#define KTOT    262144u                 /* 2048*2*64 */
#define CUT_BITS 0x40200000u            /* 2.5f : candidate cutoff, tau ~ 3.76 */
#define CAND_CAP (8u<<20)               /* 8M candidate slots */
#define BND_CAP  32768u                 /* boundary rescue slots (expect ~6600) */
#define BAND     6.0e-3f                /* +/- band around tf32 threshold */

// -------------------- device scratch (no allocations allowed) --------------------
__device__ float    g_h[NROWS * H_AE];                 // pre-topk h, 256 MiB
__device__ float    g_wdecT[INST * H_AE * IN_AE];      // W_dec transposed [i][h][a]
__device__ unsigned g_cand[CAND_CAP];                  // candidate value bits (>= 2.5f)
__device__ unsigned g_cand_idx[CAND_CAP];              // candidate flat index (row*H_AE+c)
__device__ unsigned g_cand_cnt;
__device__ unsigned g_hist1[4096];
__device__ unsigned g_hist2[4096];
__device__ unsigned g_hist3[256];
__device__ unsigned g_sel[8];   // [0]bin1 [1]krem1 [2]bin2 [3]krem2 [4]bin3 [7]k
__device__ unsigned g_bnd_idx[BND_CAP];
__device__ unsigned g_bnd_val[BND_CAP];                // exact fp32 bits (fp64-accumulated)
__device__ unsigned g_bnd_cnt;
__device__ unsigned g_nhi;                             // candidates above band (surely selected)
__device__ unsigned g_taustar;                         // exact threshold bits for boundary

// -------------------- helpers --------------------
__device__ __forceinline__ float tf32r(float x) {
    unsigned u;
    asm("cvt.rna.tf32.f32 %0, %1;" : "=r"(u) : "f"(x));
    return __uint_as_float(u);
}

__device__ __forceinline__ void mma_tf32(float* d, const unsigned* a, const unsigned* b) {
    asm volatile(
        "mma.sync.aligned.m16n8k8.row.col.f32.tf32.tf32.f32 "
        "{%0,%1,%2,%3}, {%4,%5,%6,%7}, {%8,%9}, {%0,%1,%2,%3};"
        : "+f"(d[0]), "+f"(d[1]), "+f"(d[2]), "+f"(d[3])
        : "r"(a[0]), "r"(a[1]), "r"(a[2]), "r"(a[3]), "r"(b[0]), "r"(b[1]));
}

// -------------------- K0: init counters --------------------
__global__ void init_kernel() {
    int t = threadIdx.x;
    for (int i = t; i < 4096; i += 256) { g_hist1[i] = 0u; g_hist2[i] = 0u; }
    for (int i = t; i < 256;  i += 256) g_hist3[i] = 0u;
    if (t < 8) g_sel[t] = 0u;
    if (t == 0) {
        g_cand_cnt = 0u; g_sel[7] = KTOT;
        g_bnd_cnt = 0u; g_nhi = 0u; g_taustar = 0u;
    }
}

// -------------------- K1: transpose W_dec [i][a][h] -> [i][h][a] --------------------
__global__ void transpose_kernel(const float* __restrict__ Wdec) {
    __shared__ float tile[32][33];
    int i  = blockIdx.z;
    int h0 = blockIdx.x * 32;
    int a0 = blockIdx.y * 32;
    int tx = threadIdx.x, ty = threadIdx.y;   // 32 x 8
    const float* src = Wdec + (size_t)i * IN_AE * H_AE;
    float* dst = g_wdecT + (size_t)i * H_AE * IN_AE;
#pragma unroll
    for (int r = ty; r < 32; r += 8)
        tile[r][tx] = src[(size_t)(a0 + r) * H_AE + h0 + tx];
    __syncthreads();
#pragma unroll
    for (int r = ty; r < 32; r += 8)
        dst[(size_t)(h0 + r) * IN_AE + a0 + tx] = tile[tx][r];
}

// -------------------- K2: encoder GEMM (tf32 mma.sync) + relu + candidate compaction ------
__global__ __launch_bounds__(256, 2)
void encoder_kernel(const float* __restrict__ x, const float* __restrict__ Wenc,
                    const float* __restrict__ benc) {
    __shared__ float As[128][36];
    __shared__ float Bs[128][36];
    __shared__ unsigned s_cand[2048];
    __shared__ unsigned s_cidx[2048];
    __shared__ int s_n;
    __shared__ unsigned s_base;

    const int i   = blockIdx.z;
    const int m0  = blockIdx.y * 128;
    const int n0  = blockIdx.x * 128;
    const int tid = threadIdx.x;
    const int warp = tid >> 5, lane = tid & 31;
    const int wm = warp >> 2, wn = warp & 3;
    const int gid = lane >> 2, tig = lane & 3;

    float acc[4][4][4];
#pragma unroll
    for (int a = 0; a < 4; a++)
#pragma unroll
        for (int b = 0; b < 4; b++)
#pragma unroll
            for (int c = 0; c < 4; c++) acc[a][b][c] = 0.f;

    const float* Ag = x + (size_t)i * IN_AE;                 // elem (m,k) at m*2048 + k
    const float* Bg = Wenc + (size_t)i * H_AE * IN_AE;       // elem (n,k) at n*1024 + k

    for (int k0 = 0; k0 < IN_AE; k0 += 32) {
#pragma unroll
        for (int t = 0; t < 4; t++) {
            int id  = (t << 8) + tid;          // 0..1023
            int row = id >> 3;
            int c4  = (id & 7) << 2;
            float4 va = *reinterpret_cast<const float4*>(Ag + (size_t)(m0 + row) * (INST * IN_AE) + k0 + c4);
            *reinterpret_cast<float4*>(&As[row][c4]) =
                make_float4(tf32r(va.x), tf32r(va.y), tf32r(va.z), tf32r(va.w));
            float4 vb = *reinterpret_cast<const float4*>(Bg + (size_t)(n0 + row) * IN_AE + k0 + c4);
            *reinterpret_cast<float4*>(&Bs[row][c4]) =
                make_float4(tf32r(vb.x), tf32r(vb.y), tf32r(vb.z), tf32r(vb.w));
        }
        __syncthreads();
#pragma unroll
        for (int ks = 0; ks < 4; ks++) {
            const int kb = ks * 8;
            unsigned af[4][4], bf[4][2];
#pragma unroll
            for (int mf = 0; mf < 4; mf++) {
                int r0 = (wm << 6) + (mf << 4) + gid;
                af[mf][0] = __float_as_uint(As[r0][kb + tig]);
                af[mf][1] = __float_as_uint(As[r0 + 8][kb + tig]);
                af[mf][2] = __float_as_uint(As[r0][kb + tig + 4]);
                af[mf][3] = __float_as_uint(As[r0 + 8][kb + tig + 4]);
            }
#pragma unroll
            for (int nf = 0; nf < 4; nf++) {
                int c0 = (wn << 5) + (nf << 3) + gid;
                bf[nf][0] = __float_as_uint(Bs[c0][kb + tig]);
                bf[nf][1] = __float_as_uint(Bs[c0][kb + tig + 4]);
            }
#pragma unroll
            for (int mf = 0; mf < 4; mf++)
#pragma unroll
                for (int nf = 0; nf < 4; nf++)
                    mma_tf32(acc[mf][nf], af[mf], bf[nf]);
        }
        __syncthreads();
    }

    // epilogue: bias + relu, write g_h, compact candidates (>= 2.5f) with indices
    if (tid == 0) s_n = 0;
    __syncthreads();
#pragma unroll
    for (int mf = 0; mf < 4; mf++) {
#pragma unroll
        for (int nf = 0; nf < 4; nf++) {
#pragma unroll
            for (int r = 0; r < 4; r++) {
                int m = m0 + (wm << 6) + (mf << 4) + gid + ((r >> 1) << 3);
                int c = n0 + (wn << 5) + (nf << 3) + (tig << 1) + (r & 1);
                float v = acc[mf][nf][r] + benc[i * H_AE + c];
                v = fmaxf(v, 0.f);
                unsigned flat = (unsigned)((m * INST + i) * H_AE + c);
                g_h[flat] = v;
                if (__float_as_uint(v) >= CUT_BITS) {
                    int p = atomicAdd(&s_n, 1);
                    if (p < 2048) { s_cand[p] = __float_as_uint(v); s_cidx[p] = flat; }
                }
            }
        }
    }
    __syncthreads();
    if (tid == 0) {
        int n = s_n; if (n > 2048) n = 2048;
        s_n = n;
        s_base = atomicAdd(&g_cand_cnt, (unsigned)n);
    }
    __syncthreads();
    for (int p = tid; p < s_n; p += 256) {
        unsigned dst = s_base + p;
        if (dst < CAND_CAP) { g_cand[dst] = s_cand[p]; g_cand_idx[dst] = s_cidx[p]; }
    }
}

// -------------------- K3/K5/K7: radix histograms over the candidate buffer ----------
__global__ void hist_kernel(int pass) {
    __shared__ unsigned sh[4096];
    const int nbins = (pass == 3) ? 256 : 4096;
    int tid = threadIdx.x;
    for (int i = tid; i < nbins; i += blockDim.x) sh[i] = 0u;
    __syncthreads();
    unsigned b1 = g_sel[0], b2 = g_sel[2];
    unsigned n = g_cand_cnt; if (n > CAND_CAP) n = CAND_CAP;
    for (unsigned idx = blockIdx.x * blockDim.x + tid; idx < n; idx += gridDim.x * blockDim.x) {
        unsigned bits = g_cand[idx];
        if (pass == 1) {
            atomicAdd(&sh[bits >> 20], 1u);
        } else if (pass == 2) {
            if ((bits >> 20) == b1) atomicAdd(&sh[(bits >> 8) & 0xFFFu], 1u);
        } else {
            if ((bits >> 8) == ((b1 << 12) | b2)) atomicAdd(&sh[bits & 0xFFu], 1u);
        }
    }
    __syncthreads();
    unsigned* gh = (pass == 1) ? g_hist1 : (pass == 2) ? g_hist2 : g_hist3;
    for (int i = tid; i < nbins; i += blockDim.x)
        if (sh[i]) atomicAdd(&gh[i], sh[i]);
}

// -------------------- K4/K6/K8: find bin containing the k-th largest ----------
__global__ void select_kernel(int pass) {
    __shared__ unsigned sa[4096], sb[4096];
    const unsigned* hist; int nbins, kslot, oslot;
    if (pass == 1)      { hist = g_hist1; nbins = 4096; kslot = 7; oslot = 0; }
    else if (pass == 2) { hist = g_hist2; nbins = 4096; kslot = 1; oslot = 2; }
    else                { hist = g_hist3; nbins = 256;  kslot = 3; oslot = 4; }
    int tid = threadIdx.x;
    for (int i = tid; i < nbins; i += blockDim.x) sa[i] = hist[i];
    __syncthreads();
    unsigned* src = sa; unsigned* dst = sb;
    for (int off = 1; off < nbins; off <<= 1) {
        for (int i = tid; i < nbins; i += blockDim.x) {
            unsigned v = src[i];
            if (i + off < nbins) v += src[i + off];
            dst[i] = v;
        }
        __syncthreads();
        unsigned* t = src; src = dst; dst = t;
    }
    unsigned k = g_sel[kslot];
    for (int i = tid; i < nbins; i += blockDim.x) {
        unsigned here  = src[i];
        unsigned above = (i + 1 < nbins) ? src[i + 1] : 0u;
        if (here >= k && above < k) {
            g_sel[oslot]     = (unsigned)i;
            g_sel[oslot + 1] = k - above;
        }
    }
    __syncthreads();
    if (tid == 0 && src[0] < k) { g_sel[oslot] = 0u; g_sel[oslot + 1] = 1u; }  // never in practice
}

// -------------------- K9: collect boundary candidates + count sure-selected --------
__global__ void boundary_kernel() {
    unsigned tau = (g_sel[0] << 20) | (g_sel[2] << 8) | g_sel[4];
    float tf = __uint_as_float(tau);
    float lo = tf - BAND;
    float hi = tf + BAND;
    unsigned n = g_cand_cnt; if (n > CAND_CAP) n = CAND_CAP;
    unsigned tid = blockIdx.x * blockDim.x + threadIdx.x;
    for (unsigned idx = tid; idx < n; idx += gridDim.x * blockDim.x) {
        float v = __uint_as_float(g_cand[idx]);
        bool above = (v > hi);
        bool inband = (!above) && (v >= lo);
        // warp-aggregated count of "above"
        unsigned bal = __ballot_sync(0xFFFFFFFFu, above);
        if ((threadIdx.x & 31) == 0 && bal) atomicAdd(&g_nhi, (unsigned)__popc(bal));
        if (inband) {
            unsigned p = atomicAdd(&g_bnd_cnt, 1u);
            if (p < BND_CAP) g_bnd_idx[p] = g_cand_idx[idx];
        }
    }
}

// -------------------- K10: exact (fp64) recompute of boundary dot products ---------
__global__ __launch_bounds__(256)
void recompute_kernel(const float* __restrict__ x, const float* __restrict__ Wenc,
                      const float* __restrict__ benc) {
    __shared__ double s_red[8];
    unsigned cnt = g_bnd_cnt; if (cnt > BND_CAP) cnt = BND_CAP;
    const int tid = threadIdx.x;
    const int lane = tid & 31, warp = tid >> 5;
    for (unsigned j = blockIdx.x; j < cnt; j += gridDim.x) {
        unsigned idx = g_bnd_idx[j];
        unsigned row = idx >> 14;          // /H_AE
        unsigned c   = idx & 16383u;
        unsigned ii  = row & 1u;           // INST=2
        const float* xr = x + (size_t)row * IN_AE;
        const float* wr = Wenc + ((size_t)ii * H_AE + c) * IN_AE;
        float4 xa = *reinterpret_cast<const float4*>(xr + tid * 4);
        float4 wa = *reinterpret_cast<const float4*>(wr + tid * 4);
        double s = (double)xa.x * wa.x + (double)xa.y * wa.y
                 + (double)xa.z * wa.z + (double)xa.w * wa.w;
#pragma unroll
        for (int o = 16; o > 0; o >>= 1)
            s += __shfl_down_sync(0xFFFFFFFFu, s, o);
        if (lane == 0) s_red[warp] = s;
        __syncthreads();
        if (tid == 0) {
            double t = 0.0;
#pragma unroll
            for (int w = 0; w < 8; w++) t += s_red[w];
            t += (double)benc[ii * H_AE + c];
            float f = (float)t;
            if (f < 0.f) f = 0.f;
            g_bnd_val[j] = __float_as_uint(f);
        }
        __syncthreads();
    }
}

// -------------------- K11: exact radix select among boundary values ----------------
__global__ void select4_kernel() {
    __shared__ unsigned hist[256];
    __shared__ unsigned s_prefix, s_k;
    unsigned cnt = g_bnd_cnt; if (cnt > BND_CAP) cnt = BND_CAP;
    unsigned nhi = g_nhi;
    int tid = threadIdx.x;
    if (tid == 0) {
        long long kb = (long long)KTOT - (long long)nhi;
        if (kb < 1) kb = 1;
        if (kb > (long long)cnt) kb = (long long)cnt;   // emergency clamp
        s_k = (unsigned)kb;
        s_prefix = 0u;
    }
    __syncthreads();
    if (cnt == 0) { if (tid == 0) g_taustar = 0u; return; }
    unsigned pmask = 0u;
    for (int p = 3; p >= 0; p--) {
        for (int b = tid; b < 256; b += blockDim.x) hist[b] = 0u;
        __syncthreads();
        unsigned prefix = s_prefix;
        for (unsigned j = tid; j < cnt; j += blockDim.x) {
            unsigned b = g_bnd_val[j];
            if ((b & pmask) == prefix)
                atomicAdd(&hist[(b >> (8 * p)) & 255u], 1u);
        }
        __syncthreads();
        if (tid == 0) {
            unsigned k = s_k, run = 0u, chosen = 0u, knew = 1u;
            for (int bin = 255; bin >= 0; bin--) {
                run += hist[bin];
                if (run >= k) { chosen = (unsigned)bin; knew = k - (run - hist[bin]); break; }
            }
            s_prefix = prefix | (chosen << (8 * p));
            s_k = knew;
        }
        __syncthreads();
        pmask |= (0xFFu << (8 * p));
    }
    if (tid == 0) g_taustar = s_prefix;
}

// -------------------- K12: scatter exact decisions back into g_h -------------------
__global__ void scatter_kernel() {
    unsigned cnt = g_bnd_cnt; if (cnt > BND_CAP) cnt = BND_CAP;
    unsigned ts = g_taustar;
    unsigned tid = blockIdx.x * blockDim.x + threadIdx.x;
    for (unsigned j = tid; j < cnt; j += gridDim.x * blockDim.x) {
        unsigned v = g_bnd_val[j];
        g_h[g_bnd_idx[j]] = (v >= ts) ? __uint_as_float(v) : 0.f;
    }
}

// -------------------- K13: threshold + write h, sparse decoder + write x' ----------
__global__ __launch_bounds__(256)
void final_kernel(const float* __restrict__ bdec, float* __restrict__ out) {
    __shared__ float s_val[2048];
    __shared__ unsigned short s_idx[2048];
    __shared__ int sc1[256], sc2[256];
    __shared__ int s_total;

    const int row  = blockIdx.x;        // b*INST + i
    const int inst = row & (INST - 1);
    const int tid  = threadIdx.x;
    unsigned tau = (g_sel[0] << 20) | (g_sel[2] << 8) | g_sel[4];
    const float cut = __uint_as_float(tau) - BAND;   // matches boundary_kernel lo

    float* h_out = out + (size_t)NROWS * IN_AE;
    const float4* hr = reinterpret_cast<const float4*>(g_h + (size_t)row * H_AE);
    float4* ho = reinterpret_cast<float4*>(h_out + (size_t)row * H_AE);

    // phase 1: threshold write + deterministic per-thread candidate collection
    float lv[16]; unsigned short li[16]; int ln = 0;
    for (int c = tid; c < H_AE / 4; c += 256) {
        float4 v = hr[c];
        float4 o;
        o.x = (v.x >= cut) ? v.x : 0.f;
        o.y = (v.y >= cut) ? v.y : 0.f;
        o.z = (v.z >= cut) ? v.z : 0.f;
        o.w = (v.w >= cut) ? v.w : 0.f;
        if (o.x != 0.f && ln < 16) { lv[ln] = o.x; li[ln] = (unsigned short)(c * 4 + 0); ln++; }
        if (o.y != 0.f && ln < 16) { lv[ln] = o.y; li[ln] = (unsigned short)(c * 4 + 1); ln++; }
        if (o.z != 0.f && ln < 16) { lv[ln] = o.z; li[ln] = (unsigned short)(c * 4 + 2); ln++; }
        if (o.w != 0.f && ln < 16) { lv[ln] = o.w; li[ln] = (unsigned short)(c * 4 + 3); ln++; }
        ho[c] = o;
    }
    // deterministic block inclusive scan of ln
    sc1[tid] = ln;
    __syncthreads();
    int* s1 = sc1; int* s2 = sc2;
    for (int off = 1; off < 256; off <<= 1) {
        int v = s1[tid];
        if (tid >= off) v += s1[tid - off];
        s2[tid] = v;
        __syncthreads();
        int* t = s1; s1 = s2; s2 = t;
    }
    int myoff = s1[tid] - ln;
    if (tid == 255) s_total = s1[255];
    __syncthreads();
    for (int q = 0; q < ln; q++) {
        int p = myoff + q;
        if (p < 2048) { s_val[p] = lv[q]; s_idx[p] = li[q]; }
    }
    __syncthreads();

    // phase 2: sparse decoder — each thread owns 4 output dims
    int n = s_total; if (n > 2048) n = 2048;
    float a0 = 0.f, a1 = 0.f, a2 = 0.f, a3 = 0.f;
    const float* wbase = g_wdecT + (size_t)inst * H_AE * IN_AE;
    const int a = tid << 2;
    for (int t = 0; t < n; t++) {
        float val = s_val[t];
        int hh = s_idx[t];
        float4 w = *reinterpret_cast<const float4*>(wbase + (size_t)hh * IN_AE + a);
        a0 = fmaf(val, w.x, a0);
        a1 = fmaf(val, w.y, a1);
        a2 = fmaf(val, w.z, a2);
        a3 = fmaf(val, w.w, a3);
    }
    float4 bd = *reinterpret_cast<const float4*>(bdec + inst * IN_AE + a);
    float4 r;
    r.x = fmaxf(a0 + bd.x, 0.f);
    r.y = fmaxf(a1 + bd.y, 0.f);
    r.z = fmaxf(a2 + bd.z, 0.f);
    r.w = fmaxf(a3 + bd.w, 0.f);
    *reinterpret_cast<float4*>(out + (size_t)row * IN_AE + a) = r;
}

// -------------------- launch --------------------
extern "C" void kernel_launch(void* const* d_in, const int* in_sizes, int n_in,
                              void* d_out, int out_size) {
    const float* x    = (const float*)d_in[0];
    const float* Wenc = (const float*)d_in[1];
    const float* Wdec = (const float*)d_in[2];
    const float* benc = (const float*)d_in[3];
    const float* bdec = (const float*)d_in[4];
    float* out = (float*)d_out;

    init_kernel<<<1, 256>>>();
    transpose_kernel<<<dim3(H_AE / 32, IN_AE / 32, INST), dim3(32, 8)>>>(Wdec);
    encoder_kernel<<<dim3(H_AE / 128, BATCH / 128, INST), 256>>>(x, Wenc, benc);
    hist_kernel<<<1024, 256>>>(1);
    select_kernel<<<1, 1024>>>(1);
    hist_kernel<<<1024, 256>>>(2);
    select_kernel<<<1, 1024>>>(2);
    hist_kernel<<<256, 256>>>(3);
    select_kernel<<<1, 1024>>>(3);
    boundary_kernel<<<512, 256>>>();
    recompute_kernel<<<2048, 256>>>(x, Wenc, benc);
    select4_kernel<<<1, 1024>>>();
    scatter_kernel<<<64, 256>>>();
    final_kernel<<<NROWS, 256>>>(bdec, out);
}

// round 4
// speedup vs baseline: 1.1091x; 1.1091x over previous
#include <cuda_runtime.h>
#include <cstdint>

#define BATCH   2048
#define INST    2
#define IN_AE   1024
#define H_AE    16384
#define NROWS   (BATCH*INST)            /* 4096 */
#define KTOT    262144u                 /* 2048*2*64 */
#define CUT_BITS 0x40200000u            /* 2.5f : candidate cutoff, tau ~ 3.76 */
#define CAND_CAP (8u<<20)               /* 8M candidate slots */
#define BND_CAP  32768u                 /* boundary rescue slots (expect ~6600) */
#define BAND     6.0e-3f                /* +/- band around tf32 threshold */
#define ROWCAP   512                    /* per-row selected cap (mean 64, sigma ~8) */

// -------------------- device scratch --------------------
__device__ float    g_wdecT[INST * H_AE * IN_AE];      // W_dec transposed [i][h][a]
__device__ unsigned g_cand[CAND_CAP];                  // candidate value bits (>= 2.5f)
__device__ unsigned g_cand_idx[CAND_CAP];              // candidate flat index (row*H_AE+c)
__device__ unsigned g_cand_cnt;
__device__ unsigned g_hist1[4096];
__device__ unsigned g_hist2[4096];
__device__ unsigned g_hist3[256];
__device__ unsigned g_sel[8];   // [0]bin1 [1]krem1 [2]bin2 [3]krem2 [4]bin3 [7]k
__device__ unsigned g_bnd_idx[BND_CAP];
__device__ unsigned g_bnd_val[BND_CAP];                // exact fp32 bits (fp64-accumulated)
__device__ unsigned g_bnd_cnt;
__device__ unsigned g_nhi;                             // candidates above band (surely selected)
__device__ unsigned g_taustar;                         // exact threshold bits for boundary
__device__ unsigned g_rowcnt[NROWS];
__device__ float    g_rowval[NROWS * ROWCAP];
__device__ unsigned short g_rowidx[NROWS * ROWCAP];

// -------------------- helpers --------------------
__device__ __forceinline__ unsigned tf32b(float x) {
    unsigned u;
    asm("cvt.rna.tf32.f32 %0, %1;" : "=r"(u) : "f"(x));
    return u;
}

__device__ __forceinline__ void mma_tf32(float* d, const unsigned* a, const unsigned* b) {
    asm volatile(
        "mma.sync.aligned.m16n8k8.row.col.f32.tf32.tf32.f32 "
        "{%0,%1,%2,%3}, {%4,%5,%6,%7}, {%8,%9}, {%0,%1,%2,%3};"
        : "+f"(d[0]), "+f"(d[1]), "+f"(d[2]), "+f"(d[3])
        : "r"(a[0]), "r"(a[1]), "r"(a[2]), "r"(a[3]), "r"(b[0]), "r"(b[1]));
}

__device__ __forceinline__ void cpa16(void* smem, const void* gmem) {
    unsigned sa = (unsigned)__cvta_generic_to_shared(smem);
    asm volatile("cp.async.cg.shared.global [%0], [%1], 16;" :: "r"(sa), "l"(gmem));
}
__device__ __forceinline__ void cpa_commit() { asm volatile("cp.async.commit_group;"); }
__device__ __forceinline__ void cpa_wait1()  { asm volatile("cp.async.wait_group 1;"); }

// -------------------- K: init (split into 4 launches so encoder is launch #5) ----
__global__ void init_a() { int t = threadIdx.x; for (int i = t; i < 4096; i += 256) g_hist1[i] = 0u; }
__global__ void init_b() { int t = threadIdx.x; for (int i = t; i < 4096; i += 256) g_hist2[i] = 0u; }
__global__ void init_c() {
    int t = threadIdx.x;
    for (int i = t; i < 256; i += 256) g_hist3[i] = 0u;
    if (t < 8) g_sel[t] = 0u;
    if (t == 0) { g_cand_cnt = 0u; g_sel[7] = KTOT; g_bnd_cnt = 0u; g_nhi = 0u; g_taustar = 0u; }
}
__global__ void init_d() {
    int t = blockIdx.x * blockDim.x + threadIdx.x;
    if (t < NROWS) g_rowcnt[t] = 0u;
}

// -------------------- K: transpose W_dec [i][a][h] -> [i][h][a] --------------------
__global__ void transpose_kernel(const float* __restrict__ Wdec) {
    __shared__ float tile[32][33];
    int i  = blockIdx.z;
    int h0 = blockIdx.x * 32;
    int a0 = blockIdx.y * 32;
    int tx = threadIdx.x, ty = threadIdx.y;   // 32 x 8
    const float* src = Wdec + (size_t)i * IN_AE * H_AE;
    float* dst = g_wdecT + (size_t)i * H_AE * IN_AE;
#pragma unroll
    for (int r = ty; r < 32; r += 8)
        tile[r][tx] = src[(size_t)(a0 + r) * H_AE + h0 + tx];
    __syncthreads();
#pragma unroll
    for (int r = ty; r < 32; r += 8)
        dst[(size_t)(h0 + r) * IN_AE + a0 + tx] = tile[tx][r];
}

// -------------------- K: encoder GEMM (tf32 mma.sync, cp.async 2-stage) ------------
// Writes h (thresholded at 2.5: below -> 0) directly into out's h region, and
// compacts candidates (value bits + flat index).
__global__ __launch_bounds__(256, 2)
void encoder_kernel(const float* __restrict__ x, const float* __restrict__ Wenc,
                    const float* __restrict__ benc, float* __restrict__ h_out) {
    __shared__ float As[2][128][36];
    __shared__ float Bs[2][128][36];
    __shared__ unsigned s_cand[2048];
    __shared__ unsigned s_cidx[2048];
    __shared__ int s_n;
    __shared__ unsigned s_base;

    const int i   = blockIdx.z;
    const int m0  = blockIdx.y * 128;
    const int n0  = blockIdx.x * 128;
    const int tid = threadIdx.x;
    const int warp = tid >> 5, lane = tid & 31;
    const int wm = warp >> 2, wn = warp & 3;
    const int gid = lane >> 2, tig = lane & 3;

    float acc[4][4][4];
#pragma unroll
    for (int a = 0; a < 4; a++)
#pragma unroll
        for (int b = 0; b < 4; b++)
#pragma unroll
            for (int c = 0; c < 4; c++) acc[a][b][c] = 0.f;

    const float* Ag = x + (size_t)i * IN_AE;                 // elem (m,k) at m*2048 + k
    const float* Bg = Wenc + (size_t)i * H_AE * IN_AE;       // elem (n,k) at n*1024 + k

    // prologue: stage 0
#pragma unroll
    for (int t = 0; t < 4; t++) {
        int cid = (t << 8) + tid;
        int row = cid >> 3;
        int c4  = (cid & 7) << 2;
        cpa16(&As[0][row][c4], Ag + (size_t)(m0 + row) * (INST * IN_AE) + c4);
        cpa16(&Bs[0][row][c4], Bg + (size_t)(n0 + row) * IN_AE + c4);
    }
    cpa_commit();

    const int NKT = IN_AE / 32;  // 32
    for (int kt = 0; kt < NKT; kt++) {
        int nxt = (kt + 1) & 1;
        if (kt + 1 < NKT) {
            int k0 = (kt + 1) * 32;
#pragma unroll
            for (int t = 0; t < 4; t++) {
                int cid = (t << 8) + tid;
                int row = cid >> 3;
                int c4  = (cid & 7) << 2;
                cpa16(&As[nxt][row][c4], Ag + (size_t)(m0 + row) * (INST * IN_AE) + k0 + c4);
                cpa16(&Bs[nxt][row][c4], Bg + (size_t)(n0 + row) * IN_AE + k0 + c4);
            }
        }
        cpa_commit();
        cpa_wait1();
        __syncthreads();

        int cur = kt & 1;
#pragma unroll
        for (int ks = 0; ks < 4; ks++) {
            const int kb = ks * 8;
            unsigned af[4][4], bf[4][2];
#pragma unroll
            for (int mf = 0; mf < 4; mf++) {
                int r0 = (wm << 6) + (mf << 4) + gid;
                af[mf][0] = tf32b(As[cur][r0][kb + tig]);
                af[mf][1] = tf32b(As[cur][r0 + 8][kb + tig]);
                af[mf][2] = tf32b(As[cur][r0][kb + tig + 4]);
                af[mf][3] = tf32b(As[cur][r0 + 8][kb + tig + 4]);
            }
#pragma unroll
            for (int nf = 0; nf < 4; nf++) {
                int c0 = (wn << 5) + (nf << 3) + gid;
                bf[nf][0] = tf32b(Bs[cur][c0][kb + tig]);
                bf[nf][1] = tf32b(Bs[cur][c0][kb + tig + 4]);
            }
#pragma unroll
            for (int mf = 0; mf < 4; mf++)
#pragma unroll
                for (int nf = 0; nf < 4; nf++)
                    mma_tf32(acc[mf][nf], af[mf], bf[nf]);
        }
        __syncthreads();
    }

    // epilogue: bias + relu, write thresholded h to output, compact candidates
    if (tid == 0) s_n = 0;
    __syncthreads();
#pragma unroll
    for (int mf = 0; mf < 4; mf++) {
#pragma unroll
        for (int nf = 0; nf < 4; nf++) {
#pragma unroll
            for (int r = 0; r < 4; r++) {
                int m = m0 + (wm << 6) + (mf << 4) + gid + ((r >> 1) << 3);
                int c = n0 + (wn << 5) + (nf << 3) + (tig << 1) + (r & 1);
                float v = acc[mf][nf][r] + benc[i * H_AE + c];
                v = fmaxf(v, 0.f);
                unsigned flat = (unsigned)((m * INST + i) * H_AE + c);
                bool cand = (__float_as_uint(v) >= CUT_BITS);
                h_out[flat] = cand ? v : 0.f;
                if (cand) {
                    int p = atomicAdd(&s_n, 1);
                    if (p < 2048) { s_cand[p] = __float_as_uint(v); s_cidx[p] = flat; }
                }
            }
        }
    }
    __syncthreads();
    if (tid == 0) {
        int n = s_n; if (n > 2048) n = 2048;
        s_n = n;
        s_base = atomicAdd(&g_cand_cnt, (unsigned)n);
    }
    __syncthreads();
    for (int p = tid; p < s_n; p += 256) {
        unsigned dst = s_base + p;
        if (dst < CAND_CAP) { g_cand[dst] = s_cand[p]; g_cand_idx[dst] = s_cidx[p]; }
    }
}

// -------------------- K: radix histograms over the candidate buffer ----------------
__global__ void hist_kernel(int pass) {
    __shared__ unsigned sh[4096];
    const int nbins = (pass == 3) ? 256 : 4096;
    int tid = threadIdx.x;
    for (int i = tid; i < nbins; i += blockDim.x) sh[i] = 0u;
    __syncthreads();
    unsigned b1 = g_sel[0], b2 = g_sel[2];
    unsigned n = g_cand_cnt; if (n > CAND_CAP) n = CAND_CAP;
    for (unsigned idx = blockIdx.x * blockDim.x + tid; idx < n; idx += gridDim.x * blockDim.x) {
        unsigned bits = g_cand[idx];
        if (pass == 1) {
            atomicAdd(&sh[bits >> 20], 1u);
        } else if (pass == 2) {
            if ((bits >> 20) == b1) atomicAdd(&sh[(bits >> 8) & 0xFFFu], 1u);
        } else {
            if ((bits >> 8) == ((b1 << 12) | b2)) atomicAdd(&sh[bits & 0xFFu], 1u);
        }
    }
    __syncthreads();
    unsigned* gh = (pass == 1) ? g_hist1 : (pass == 2) ? g_hist2 : g_hist3;
    for (int i = tid; i < nbins; i += blockDim.x)
        if (sh[i]) atomicAdd(&gh[i], sh[i]);
}

// -------------------- K: find bin containing the k-th largest ----------------------
__global__ void select_kernel(int pass) {
    __shared__ unsigned sa[4096], sb[4096];
    const unsigned* hist; int nbins, kslot, oslot;
    if (pass == 1)      { hist = g_hist1; nbins = 4096; kslot = 7; oslot = 0; }
    else if (pass == 2) { hist = g_hist2; nbins = 4096; kslot = 1; oslot = 2; }
    else                { hist = g_hist3; nbins = 256;  kslot = 3; oslot = 4; }
    int tid = threadIdx.x;
    for (int i = tid; i < nbins; i += blockDim.x) sa[i] = hist[i];
    __syncthreads();
    unsigned* src = sa; unsigned* dst = sb;
    for (int off = 1; off < nbins; off <<= 1) {
        for (int i = tid; i < nbins; i += blockDim.x) {
            unsigned v = src[i];
            if (i + off < nbins) v += src[i + off];
            dst[i] = v;
        }
        __syncthreads();
        unsigned* t = src; src = dst; dst = t;
    }
    unsigned k = g_sel[kslot];
    for (int i = tid; i < nbins; i += blockDim.x) {
        unsigned here  = src[i];
        unsigned above = (i + 1 < nbins) ? src[i + 1] : 0u;
        if (here >= k && above < k) {
            g_sel[oslot]     = (unsigned)i;
            g_sel[oslot + 1] = k - above;
        }
    }
    __syncthreads();
    if (tid == 0 && src[0] < k) { g_sel[oslot] = 0u; g_sel[oslot + 1] = 1u; }  // never in practice
}

// -------------------- K: collect boundary candidates + count sure-selected ---------
__global__ void boundary_kernel() {
    unsigned tau = (g_sel[0] << 20) | (g_sel[2] << 8) | g_sel[4];
    float tf = __uint_as_float(tau);
    float lo = tf - BAND;
    float hi = tf + BAND;
    unsigned n = g_cand_cnt; if (n > CAND_CAP) n = CAND_CAP;
    unsigned tid = blockIdx.x * blockDim.x + threadIdx.x;
    for (unsigned idx = tid; idx < n; idx += gridDim.x * blockDim.x) {
        float v = __uint_as_float(g_cand[idx]);
        bool above = (v > hi);
        bool inband = (!above) && (v >= lo);
        unsigned bal = __ballot_sync(0xFFFFFFFFu, above);
        if ((threadIdx.x & 31) == 0 && bal) atomicAdd(&g_nhi, (unsigned)__popc(bal));
        if (inband) {
            unsigned p = atomicAdd(&g_bnd_cnt, 1u);
            if (p < BND_CAP) g_bnd_idx[p] = g_cand_idx[idx];
        }
    }
}

// -------------------- K: exact (fp64) recompute of boundary dot products -----------
__global__ __launch_bounds__(256)
void recompute_kernel(const float* __restrict__ x, const float* __restrict__ Wenc,
                      const float* __restrict__ benc) {
    __shared__ double s_red[8];
    unsigned cnt = g_bnd_cnt; if (cnt > BND_CAP) cnt = BND_CAP;
    const int tid = threadIdx.x;
    const int lane = tid & 31, warp = tid >> 5;
    for (unsigned j = blockIdx.x; j < cnt; j += gridDim.x) {
        unsigned idx = g_bnd_idx[j];
        unsigned row = idx >> 14;          // /H_AE
        unsigned c   = idx & 16383u;
        unsigned ii  = row & 1u;           // INST=2
        const float* xr = x + (size_t)row * IN_AE;
        const float* wr = Wenc + ((size_t)ii * H_AE + c) * IN_AE;
        float4 xa = *reinterpret_cast<const float4*>(xr + tid * 4);
        float4 wa = *reinterpret_cast<const float4*>(wr + tid * 4);
        double s = (double)xa.x * wa.x + (double)xa.y * wa.y
                 + (double)xa.z * wa.z + (double)xa.w * wa.w;
#pragma unroll
        for (int o = 16; o > 0; o >>= 1)
            s += __shfl_down_sync(0xFFFFFFFFu, s, o);
        if (lane == 0) s_red[warp] = s;
        __syncthreads();
        if (tid == 0) {
            double t = 0.0;
#pragma unroll
            for (int w = 0; w < 8; w++) t += s_red[w];
            t += (double)benc[ii * H_AE + c];
            float f = (float)t;
            if (f < 0.f) f = 0.f;
            g_bnd_val[j] = __float_as_uint(f);
        }
        __syncthreads();
    }
}

// -------------------- K: exact radix select among boundary values ------------------
__global__ void select4_kernel() {
    __shared__ unsigned hist[256];
    __shared__ unsigned s_prefix, s_k;
    unsigned cnt = g_bnd_cnt; if (cnt > BND_CAP) cnt = BND_CAP;
    unsigned nhi = g_nhi;
    int tid = threadIdx.x;
    if (tid == 0) {
        long long kb = (long long)KTOT - (long long)nhi;
        if (kb < 1) kb = 1;
        if (kb > (long long)cnt) kb = (long long)cnt;
        s_k = (unsigned)kb;
        s_prefix = 0u;
    }
    __syncthreads();
    if (cnt == 0) { if (tid == 0) g_taustar = 0u; return; }
    unsigned pmask = 0u;
    for (int p = 3; p >= 0; p--) {
        for (int b = tid; b < 256; b += blockDim.x) hist[b] = 0u;
        __syncthreads();
        unsigned prefix = s_prefix;
        for (unsigned j = tid; j < cnt; j += blockDim.x) {
            unsigned b = g_bnd_val[j];
            if ((b & pmask) == prefix)
                atomicAdd(&hist[(b >> (8 * p)) & 255u], 1u);
        }
        __syncthreads();
        if (tid == 0) {
            unsigned k = s_k, run = 0u, chosen = 0u, knew = 1u;
            for (int bin = 255; bin >= 0; bin--) {
                run += hist[bin];
                if (run >= k) { chosen = (unsigned)bin; knew = k - (run - hist[bin]); break; }
            }
            s_prefix = prefix | (chosen << (8 * p));
            s_k = knew;
        }
        __syncthreads();
        pmask |= (0xFFu << (8 * p));
    }
    if (tid == 0) g_taustar = s_prefix;
}

// -------------------- K: rowlist build (above band) + zero below-band in h_out -----
__global__ void rowlist_kernel(float* __restrict__ h_out) {
    unsigned tau = (g_sel[0] << 20) | (g_sel[2] << 8) | g_sel[4];
    float tf = __uint_as_float(tau);
    float lo = tf - BAND;
    float hi = tf + BAND;
    unsigned n = g_cand_cnt; if (n > CAND_CAP) n = CAND_CAP;
    unsigned tid = blockIdx.x * blockDim.x + threadIdx.x;
    for (unsigned j = tid; j < n; j += gridDim.x * blockDim.x) {
        float v = __uint_as_float(g_cand[j]);
        unsigned idx = g_cand_idx[j];
        if (v > hi) {
            unsigned row = idx >> 14;
            unsigned p = atomicAdd(&g_rowcnt[row], 1u);
            if (p < ROWCAP) {
                g_rowval[row * ROWCAP + p] = v;
                g_rowidx[row * ROWCAP + p] = (unsigned short)(idx & 16383u);
            }
        } else if (v < lo) {
            h_out[idx] = 0.f;
        }
    }
}

// -------------------- K: in-band resolve (exact value or zero) + rowlist push ------
__global__ void inband_kernel(float* __restrict__ h_out) {
    unsigned cnt = g_bnd_cnt; if (cnt > BND_CAP) cnt = BND_CAP;
    unsigned ts = g_taustar;
    unsigned tid = blockIdx.x * blockDim.x + threadIdx.x;
    for (unsigned j = tid; j < cnt; j += gridDim.x * blockDim.x) {
        unsigned vb = g_bnd_val[j];
        unsigned idx = g_bnd_idx[j];
        bool sel = (vb >= ts);
        h_out[idx] = sel ? __uint_as_float(vb) : 0.f;
        if (sel) {
            unsigned row = idx >> 14;
            unsigned p = atomicAdd(&g_rowcnt[row], 1u);
            if (p < ROWCAP) {
                g_rowval[row * ROWCAP + p] = __uint_as_float(vb);
                g_rowidx[row * ROWCAP + p] = (unsigned short)(idx & 16383u);
            }
        }
    }
}

// -------------------- K: sparse decoder from row lists -----------------------------
__global__ __launch_bounds__(256)
void decoder_kernel(const float* __restrict__ bdec, float* __restrict__ out) {
    __shared__ float s_val[ROWCAP];
    __shared__ unsigned short s_idx[ROWCAP];
    const int row  = blockIdx.x;
    const int inst = row & (INST - 1);
    const int tid  = threadIdx.x;
    int n = (int)g_rowcnt[row]; if (n > ROWCAP) n = ROWCAP;
    for (int p = tid; p < n; p += 256) {
        s_val[p] = g_rowval[row * ROWCAP + p];
        s_idx[p] = g_rowidx[row * ROWCAP + p];
    }
    __syncthreads();
    float a0 = 0.f, a1 = 0.f, a2 = 0.f, a3 = 0.f;
    const float* wbase = g_wdecT + (size_t)inst * H_AE * IN_AE;
    const int a = tid << 2;
    for (int t = 0; t < n; t++) {
        float val = s_val[t];
        int hh = s_idx[t];
        float4 w = *reinterpret_cast<const float4*>(wbase + (size_t)hh * IN_AE + a);
        a0 = fmaf(val, w.x, a0);
        a1 = fmaf(val, w.y, a1);
        a2 = fmaf(val, w.z, a2);
        a3 = fmaf(val, w.w, a3);
    }
    float4 bd = *reinterpret_cast<const float4*>(bdec + inst * IN_AE + a);
    float4 r;
    r.x = fmaxf(a0 + bd.x, 0.f);
    r.y = fmaxf(a1 + bd.y, 0.f);
    r.z = fmaxf(a2 + bd.z, 0.f);
    r.w = fmaxf(a3 + bd.w, 0.f);
    *reinterpret_cast<float4*>(out + (size_t)row * IN_AE + a) = r;
}

// -------------------- launch --------------------
extern "C" void kernel_launch(void* const* d_in, const int* in_sizes, int n_in,
                              void* d_out, int out_size) {
    const float* x    = (const float*)d_in[0];
    const float* Wenc = (const float*)d_in[1];
    const float* Wdec = (const float*)d_in[2];
    const float* benc = (const float*)d_in[3];
    const float* bdec = (const float*)d_in[4];
    float* out = (float*)d_out;
    float* h_out = out + (size_t)NROWS * IN_AE;

    init_a<<<1, 256>>>();                                          // launch 0
    init_b<<<1, 256>>>();                                          // launch 1
    init_c<<<1, 256>>>();                                          // launch 2
    init_d<<<16, 256>>>();                                         // launch 3
    transpose_kernel<<<dim3(H_AE / 32, IN_AE / 32, INST), dim3(32, 8)>>>(Wdec);  // launch 4
    encoder_kernel<<<dim3(H_AE / 128, BATCH / 128, INST), 256>>>(x, Wenc, benc, h_out);  // launch 5 (ncu -s 5)
    hist_kernel<<<1024, 256>>>(1);
    select_kernel<<<1, 1024>>>(1);
    hist_kernel<<<1024, 256>>>(2);
    select_kernel<<<1, 1024>>>(2);
    hist_kernel<<<256, 256>>>(3);
    select_kernel<<<1, 1024>>>(3);
    boundary_kernel<<<512, 256>>>();
    recompute_kernel<<<2048, 256>>>(x, Wenc, benc);
    select4_kernel<<<1, 1024>>>();
    rowlist_kernel<<<512, 256>>>(h_out);
    inband_kernel<<<64, 256>>>(h_out);
    decoder_kernel<<<NROWS, 256>>>(bdec, out);
}